// round 4
// baseline (speedup 1.0000x reference)
#include <cuda_runtime.h>
#include <cuda_bf16.h>
#include <cstdint>

// RotationComponent: w_rotated = w @ rot, a_rotated = x @ rot, where rot is a
// normalized randomized Hadamard matrix: rot[i,j] = H[i,j] * rot[0,j], H the
// 4096x4096 Sylvester Hadamard (symmetric, H[0,:] = +1). Hence
//   (v @ rot)[j] = FWHT(v)[j] * rot[0,j]
// with the per-column scale (+-1/64, exact in fp32) read from rot's row 0.
//
// One CTA per row. Shuffle-free FWHT via two conflict-free smem transposes:
//   P1: regs = i-bits {11..8}  (i = r*256 + t; coalesced scalar LDG)
//   T1: padded smem (phys = i + (i>>5)); write stride-1 banks
//   P2: regs = i-bits {7..4}   (i = A*256 + r2*16 + B; lane bit a at A-bit-1
//       gives bank weight 16 -> 32 distinct banks per access)
//   T2: write back to the same per-thread address set (no sync needed before)
//   P3: regs = i-bits {3..0}   (i = t*16 + rA; banks = 16*(t&1)+(t>>1)+rA, all
//       distinct) -> thread holds 16 CONSECUTIVE outputs
// Epilogue: 4x LDG.128 of rot row 0 (L1-hit) + 4x STG.128.

#define DIM 4096
#define W_ROWS 4096
#define X_ROWS 8192   // 4 * 2048
#define THREADS 256
#define SMEM_WORDS (DIM + DIM / 32)   // pad one word per 32

__global__ __launch_bounds__(THREADS)
void fwht_rotate_kernel(const float* __restrict__ w,
                        const float* __restrict__ x,
                        const float* __restrict__ rot,
                        float* __restrict__ out)
{
    __shared__ float smem[SMEM_WORDS];

    const int row  = blockIdx.x;
    const int t    = threadIdx.x;
    const int lane = t & 31;
    const int warp = t >> 5;

    const float* src = (row < W_ROWS)
        ? (w + (size_t)row * DIM)
        : (x + (size_t)(row - W_ROWS) * DIM);

    float v[16];

    // ---- P1 load: v[r] = src[r*256 + t] (coalesced 128B per warp instr) ----
    #pragma unroll
    for (int r = 0; r < 16; r++) {
        v[r] = src[r * 256 + t];
    }

    // ---- P1 butterflies: i-bits {11..8} ----
    #pragma unroll
    for (int m = 8; m >= 1; m >>= 1) {
        #pragma unroll
        for (int r = 0; r < 16; r++) {
            if ((r & m) == 0) {
                float a = v[r], b = v[r | m];
                v[r]     = a + b;
                v[r | m] = a - b;
            }
        }
    }

    // ---- T1 write: phys(r*256+t) = r*264 + warp*33 + lane (stride-1 banks) --
    #pragma unroll
    for (int r = 0; r < 16; r++) {
        smem[r * 264 + warp * 33 + lane] = v[r];
    }
    __syncthreads();

    // ---- P2 read: i = A*256 + r2*16 + B ----
    //   a = lane>>4 placed at A bit 1 (bank weight 8*2 = 16), B = lane&15.
    //   phys = A*264 + r2*16 + (r2>>1) + B; banks = 16a + B + const -> 32 distinct.
    const int a2 = lane >> 4;
    const int B2 = lane & 15;
    const int A2 = ((warp >> 2) << 3) | (((warp >> 1) & 1) << 2) | (a2 << 1) | (warp & 1);
    const int base2 = A2 * 264 + B2;
    #pragma unroll
    for (int r2 = 0; r2 < 16; r2++) {
        v[r2] = smem[base2 + r2 * 16 + (r2 >> 1)];
    }

    // ---- P2 butterflies: i-bits {7..4} ----
    #pragma unroll
    for (int m = 8; m >= 1; m >>= 1) {
        #pragma unroll
        for (int r2 = 0; r2 < 16; r2++) {
            if ((r2 & m) == 0) {
                float a = v[r2], b = v[r2 | m];
                v[r2]     = a + b;
                v[r2 | m] = a - b;
            }
        }
    }

    // ---- T2 write back (same per-thread address set; no pre-sync needed) ----
    #pragma unroll
    for (int r2 = 0; r2 < 16; r2++) {
        smem[base2 + r2 * 16 + (r2 >> 1)] = v[r2];
    }
    __syncthreads();

    // ---- P3 read: i = t*16 + rA; phys = t*16 + (t>>1) + rA ----
    //   banks = 16*(t&1) + (t>>1) + rA -> 32 distinct per instruction.
    const int base3 = t * 16 + (t >> 1);
    #pragma unroll
    for (int rA = 0; rA < 16; rA++) {
        v[rA] = smem[base3 + rA];
    }

    // ---- P3 butterflies: i-bits {3..0} ----
    #pragma unroll
    for (int m = 8; m >= 1; m >>= 1) {
        #pragma unroll
        for (int rA = 0; rA < 16; rA++) {
            if ((rA & m) == 0) {
                float a = v[rA], b = v[rA | m];
                v[rA]     = a + b;
                v[rA | m] = a - b;
            }
        }
    }

    // ---- Epilogue: thread owns outputs i = t*16 .. t*16+15 (consecutive).
    //      Scale by rot[0, i] (exactly +-1/64; LDG.128 L1-hit) and STG.128.
    const float* rrow = rot + t * 16;
    float*       dst  = out + (size_t)row * DIM + t * 16;
    #pragma unroll
    for (int q = 0; q < 4; q++) {
        float4 s = __ldg((const float4*)(rrow + q * 4));
        float4 o;
        o.x = v[q * 4 + 0] * s.x;
        o.y = v[q * 4 + 1] * s.y;
        o.z = v[q * 4 + 2] * s.z;
        o.w = v[q * 4 + 3] * s.w;
        *(float4*)(dst + q * 4) = o;
    }
}

extern "C" void kernel_launch(void* const* d_in, const int* in_sizes, int n_in,
                              void* d_out, int out_size)
{
    const float* w   = (const float*)d_in[0];   // [4096, 4096]
    const float* x   = (const float*)d_in[1];   // [4, 2048, 4096]
    const float* rot = (const float*)d_in[2];   // [4096, 4096]
    float* out = (float*)d_out;                 // w_rotated then a_rotated

    (void)in_sizes; (void)n_in; (void)out_size;

    fwht_rotate_kernel<<<W_ROWS + X_ROWS, THREADS>>>(w, x, rot, out);
}

// round 5
// speedup vs baseline: 1.4340x; 1.4340x over previous
#include <cuda_runtime.h>
#include <cuda_bf16.h>
#include <cstdint>

// RotationComponent: w_rotated = w @ rot, a_rotated = x @ rot, where rot is a
// normalized randomized Hadamard matrix: rot[i,j] = H[i,j] * rot[0,j], H the
// 4096x4096 Sylvester Hadamard (symmetric, H[0,:] = +1). Hence
//   (v @ rot)[j] = FWHT(v)[j] * rot[0,j]
// with per-column scales read from rot's first row (exact).
//
// One CTA per row. Shuffle-free FWHT; since butterfly stages commute, phases:
//   P1: regs = i-bits {9..6}   i = (t>>6)*1024 + r*64 + (t&63)   (LDG coalesced)
//   P2: regs = i-bits {5..2}   i = J*64 + r*4 + e2, J = warp*8 + lane{4..2},
//                              e2 = lane{1..0}                    (smem only)
//   P3: regs = i-bits {11,10,1,0}  i = c*1024 + t*4 + e
//       -> 4 aligned float4 outputs: STG.128 / rot LDG.128, 4 lines per instr
// SMEM XOR swizzle: col' = (i&31) ^ f(i>>5), f(u) = (((u>>1)&7)<<2)|(u&3);
// all four smem access patterns are bank-conflict-free under this swizzle.

#define DIM 4096
#define W_ROWS 4096
#define X_ROWS 8192   // 4 * 2048
#define THREADS 256

__device__ __forceinline__ int swz(int i)
{
    const int row = i >> 5;
    const int col = i & 31;
    const int f   = (((row >> 1) & 7) << 2) | (row & 3);
    return (row << 5) | (col ^ f);
}

__global__ __launch_bounds__(THREADS)
void fwht_rotate_kernel(const float* __restrict__ w,
                        const float* __restrict__ x,
                        const float* __restrict__ rot,
                        float* __restrict__ out)
{
    __shared__ float smem[DIM];

    const int row  = blockIdx.x;
    const int t    = threadIdx.x;
    const int lane = t & 31;
    const int warp = t >> 5;

    const float* src = (row < W_ROWS)
        ? (w + (size_t)row * DIM)
        : (x + (size_t)(row - W_ROWS) * DIM);

    float v[16];

    // ---- P1: i = (t>>6)*1024 + r*64 + (t&63); LDG coalesced (1 line/instr) --
    const int p1_base = (t >> 6) * 1024 + (t & 63);
    #pragma unroll
    for (int r = 0; r < 16; r++) {
        v[r] = src[p1_base + r * 64];
    }

    // ---- P1 butterflies: i-bits {9..6} (r bits 3..0) ----
    #pragma unroll
    for (int m = 8; m >= 1; m >>= 1) {
        #pragma unroll
        for (int r = 0; r < 16; r++) {
            if ((r & m) == 0) {
                float a = v[r], b = v[r | m];
                v[r]     = a + b;
                v[r | m] = a - b;
            }
        }
    }

    // ---- T1: write swizzled smem (per instr: banks = lane ^ const, CF) ----
    #pragma unroll
    for (int r = 0; r < 16; r++) {
        smem[swz(p1_base + r * 64)] = v[r];
    }
    __syncthreads();

    // ---- P2: i = J*64 + r*4 + e2; J = warp*8 + lane{4..2}, e2 = lane{1..0} --
    const int J2      = warp * 8 + ((lane >> 2) & 7);
    const int e2      = lane & 3;
    const int p2_base = J2 * 64 + e2;
    #pragma unroll
    for (int r = 0; r < 16; r++) {
        v[r] = smem[swz(p2_base + r * 4)];
    }

    // ---- P2 butterflies: i-bits {5..2} ----
    #pragma unroll
    for (int m = 8; m >= 1; m >>= 1) {
        #pragma unroll
        for (int r = 0; r < 16; r++) {
            if ((r & m) == 0) {
                float a = v[r], b = v[r | m];
                v[r]     = a + b;
                v[r | m] = a - b;
            }
        }
    }

    // ---- T2: write back to the same per-thread addresses (no hazard) ----
    #pragma unroll
    for (int r = 0; r < 16; r++) {
        smem[swz(p2_base + r * 4)] = v[r];
    }
    __syncthreads();

    // ---- P3: i = c*1024 + t*4 + e; regs = bits {11,10,1,0} ----
    const int p3_base = t * 4;
    #pragma unroll
    for (int c = 0; c < 4; c++) {
        #pragma unroll
        for (int e = 0; e < 4; e++) {
            v[c * 4 + e] = smem[swz(c * 1024 + p3_base + e)];
        }
    }

    // ---- P3 butterflies: bit11 <-> c1 (mask 8), bit10 <-> c0 (mask 4),
    //      bit1 <-> e1 (mask 2), bit0 <-> e0 (mask 1) ----
    #pragma unroll
    for (int m = 8; m >= 1; m >>= 1) {
        #pragma unroll
        for (int r = 0; r < 16; r++) {
            if ((r & m) == 0) {
                float a = v[r], b = v[r | m];
                v[r]     = a + b;
                v[r | m] = a - b;
            }
        }
    }

    // ---- Epilogue: 4 aligned float4 stores at i = c*1024 + t*4, scaled by
    //      rot[0, i] (LDG.128, L1-hit after first CTAs) ----
    float* dst = out + (size_t)row * DIM;
    #pragma unroll
    for (int c = 0; c < 4; c++) {
        const int idx = c * 1024 + p3_base;
        float4 s = __ldg((const float4*)(rot + idx));
        float4 o;
        o.x = v[c * 4 + 0] * s.x;
        o.y = v[c * 4 + 1] * s.y;
        o.z = v[c * 4 + 2] * s.z;
        o.w = v[c * 4 + 3] * s.w;
        *(float4*)(dst + idx) = o;
    }
}

extern "C" void kernel_launch(void* const* d_in, const int* in_sizes, int n_in,
                              void* d_out, int out_size)
{
    const float* w   = (const float*)d_in[0];   // [4096, 4096]
    const float* x   = (const float*)d_in[1];   // [4, 2048, 4096]
    const float* rot = (const float*)d_in[2];   // [4096, 4096]
    float* out = (float*)d_out;                 // w_rotated then a_rotated

    (void)in_sizes; (void)n_in; (void)out_size;

    fwht_rotate_kernel<<<W_ROWS + X_ROWS, THREADS>>>(w, x, rot, out);
}

// round 6
// speedup vs baseline: 1.4790x; 1.0314x over previous
#include <cuda_runtime.h>
#include <cuda_bf16.h>
#include <cstdint>

// RotationComponent: w_rotated = w @ rot, a_rotated = x @ rot, where rot is a
// normalized randomized Hadamard matrix: rot[i,j] = H[i,j] * rot[0,j], H the
// 4096x4096 Sylvester Hadamard (symmetric, H[0,:] = +1). Hence
//   (v @ rot)[j] = FWHT(v)[j] * rot[0,j]
// with per-column scales read from rot's first row (exact).
//
// One CTA per row. Shuffle-free FWHT (stages commute), phases:
//   P1: regs = i-bits {9..6}   i = (t>>6)*1024 + r*64 + (t&63)   (LDG coalesced)
//   P2: regs = i-bits {5..2}   i = J*64 + r*4 + e2, J = warp*8 + lane{4..2},
//                              e2 = lane{1..0}                    (smem only)
//   P3: regs = i-bits {11,10,1,0}  i = c*1024 + t*4 + e
//       -> 4 aligned float4: LDS.128 from smem, rot LDG.128, STG.128
// SMEM swizzle (16B-granular, 2 SASS ops): phys = i ^ ((i>>4) & 28), i.e.
// XOR i-bits{8..6} into i-bits{4..2}. Verified conflict-free for all four
// smem patterns and preserves 16B contiguity for the P3 LDS.128.

#define DIM 4096
#define W_ROWS 4096
#define X_ROWS 8192   // 4 * 2048
#define THREADS 256

__device__ __forceinline__ int swz(int i)
{
    return i ^ ((i >> 4) & 28);
}

__global__ __launch_bounds__(THREADS)
void fwht_rotate_kernel(const float* __restrict__ w,
                        const float* __restrict__ x,
                        const float* __restrict__ rot,
                        float* __restrict__ out)
{
    __shared__ float smem[DIM];

    const int row  = blockIdx.x;
    const int t    = threadIdx.x;
    const int lane = t & 31;
    const int warp = t >> 5;

    const float* src = (row < W_ROWS)
        ? (w + (size_t)row * DIM)
        : (x + (size_t)(row - W_ROWS) * DIM);

    float v[16];

    // ---- P1: i = (t>>6)*1024 + r*64 + (t&63); LDG coalesced (1 line/instr) --
    const int p1_base = (t >> 6) * 1024 + (t & 63);
    #pragma unroll
    for (int r = 0; r < 16; r++) {
        v[r] = src[p1_base + r * 64];
    }

    // ---- P1 butterflies: i-bits {9..6} (r bits 3..0) ----
    #pragma unroll
    for (int m = 8; m >= 1; m >>= 1) {
        #pragma unroll
        for (int r = 0; r < 16; r++) {
            if ((r & m) == 0) {
                float a = v[r], b = v[r | m];
                v[r]     = a + b;
                v[r | m] = a - b;
            }
        }
    }

    // ---- T1: swizzled smem write (banks = lane ^ const per instr, CF) ----
    #pragma unroll
    for (int r = 0; r < 16; r++) {
        smem[swz(p1_base + r * 64)] = v[r];
    }
    __syncthreads();

    // ---- P2: i = J*64 + r*4 + e2; J = warp*8 + lane{4..2}, e2 = lane{1..0} --
    const int p2_base = (warp * 8 + ((lane >> 2) & 7)) * 64 + (lane & 3);
    #pragma unroll
    for (int r = 0; r < 16; r++) {
        v[r] = smem[swz(p2_base + r * 4)];
    }

    // ---- P2 butterflies: i-bits {5..2} ----
    #pragma unroll
    for (int m = 8; m >= 1; m >>= 1) {
        #pragma unroll
        for (int r = 0; r < 16; r++) {
            if ((r & m) == 0) {
                float a = v[r], b = v[r | m];
                v[r]     = a + b;
                v[r | m] = a - b;
            }
        }
    }

    // ---- T2: write back to the same per-thread addresses (no hazard) ----
    #pragma unroll
    for (int r = 0; r < 16; r++) {
        smem[swz(p2_base + r * 4)] = v[r];
    }
    __syncthreads();

    // ---- P3: i = c*1024 + t*4 + e; LDS.128 (swizzle preserves 16B blocks) --
    const int p3_base = t * 4;
    #pragma unroll
    for (int c = 0; c < 4; c++) {
        float4 q = *(const float4*)(smem + swz(c * 1024 + p3_base));
        v[c * 4 + 0] = q.x;
        v[c * 4 + 1] = q.y;
        v[c * 4 + 2] = q.z;
        v[c * 4 + 3] = q.w;
    }

    // ---- P3 butterflies: bit11<->c1 (mask 8), bit10<->c0 (mask 4),
    //      bit1<->e1 (mask 2), bit0<->e0 (mask 1) ----
    #pragma unroll
    for (int m = 8; m >= 1; m >>= 1) {
        #pragma unroll
        for (int r = 0; r < 16; r++) {
            if ((r & m) == 0) {
                float a = v[r], b = v[r | m];
                v[r]     = a + b;
                v[r | m] = a - b;
            }
        }
    }

    // ---- Epilogue: 4 aligned float4 stores at i = c*1024 + t*4, scaled by
    //      rot[0, i] (LDG.128, L1-hit after first CTAs) ----
    float* dst = out + (size_t)row * DIM;
    #pragma unroll
    for (int c = 0; c < 4; c++) {
        const int idx = c * 1024 + p3_base;
        float4 s = __ldg((const float4*)(rot + idx));
        float4 o;
        o.x = v[c * 4 + 0] * s.x;
        o.y = v[c * 4 + 1] * s.y;
        o.z = v[c * 4 + 2] * s.z;
        o.w = v[c * 4 + 3] * s.w;
        *(float4*)(dst + idx) = o;
    }
}

extern "C" void kernel_launch(void* const* d_in, const int* in_sizes, int n_in,
                              void* d_out, int out_size)
{
    const float* w   = (const float*)d_in[0];   // [4096, 4096]
    const float* x   = (const float*)d_in[1];   // [4, 2048, 4096]
    const float* rot = (const float*)d_in[2];   // [4096, 4096]
    float* out = (float*)d_out;                 // w_rotated then a_rotated

    (void)in_sizes; (void)n_in; (void)out_size;

    fwht_rotate_kernel<<<W_ROWS + X_ROWS, THREADS>>>(w, x, rot, out);
}